// round 13
// baseline (speedup 1.0000x reference)
#include <cuda_runtime.h>
#include <cstdint>

#define BB      8
#define CTOT    256
#define HH      96
#define WW      128
#define THREADS 288                // 9 warps, one dy each
#define CHS     (HH*WW)            // channel stride (floats)
#define CHS4    (CHS/4)            // channel stride (float4)

typedef unsigned long long ull;

__device__ float4 g_zero4 = {0.f, 0.f, 0.f, 0.f};   // OOB target (stride-0 lanes)

__device__ __forceinline__ ull pk(float lo, float hi) {
    ull r;
    asm("mov.b64 %0, {%1,%2};" : "=l"(r) : "f"(lo), "f"(hi));
    return r;
}
__device__ __forceinline__ float2 upk(ull v) {
    float2 f;
    asm("mov.b64 {%0,%1}, %2;" : "=f"(f.x), "=f"(f.y) : "l"(v));
    return f;
}
__device__ __forceinline__ void ffma2(ull& d, ull a, ull b) {
    asm("fma.rn.f32x2 %0, %1, %2, %0;" : "+l"(d) : "l"(a), "l"(b));
}

// One channel: window f[0..11] = qL | m | qR, 11 packs, 18 packed FMAs.
__device__ __forceinline__ void compute_channel(float4 a, float4 qL, float4 m,
                                                float4 qR, ull acc[9][2])
{
    ull A0 = pk(a.x, a.y);
    ull A1 = pk(a.z, a.w);

    ull E[6], O[5];
    E[0] = pk(qL.x, qL.y); E[1] = pk(qL.z, qL.w);
    E[2] = pk(m.x,  m.y ); E[3] = pk(m.z,  m.w );
    E[4] = pk(qR.x, qR.y); E[5] = pk(qR.z, qR.w);
    O[0] = pk(qL.y, qL.z); O[1] = pk(qL.w, m.x );
    O[2] = pk(m.y,  m.z ); O[3] = pk(m.w,  qR.x);
    O[4] = pk(qR.y, qR.z);

#pragma unroll
    for (int d = 0; d < 9; d++) {
        ull b0 = (d & 1) ? O[(d >> 1)]     : E[(d >> 1)];
        ull b1 = (d & 1) ? O[(d >> 1) + 1] : E[(d >> 1) + 1];
        ffma2(acc[d][0], A0, b0);
        ffma2(acc[d][1], A1, b1);
    }
}

__global__ void __launch_bounds__(THREADS, 2)
corr_kernel(const float* __restrict__ in1, const float* __restrict__ in2,
            float* __restrict__ out)
{
    const int tid  = threadIdx.x;
    const int warp = tid >> 5;         // dy 0..8
    const int lane = tid & 31;
    const int x0   = lane << 2;        // 4 px per lane

    const int bx = blockIdx.x;
    const int b  = bx / HH;
    const int h0 = bx - b * HH;        // output row

    const int hB = h0 + warp - 4;      // this warp's in2 source row
    const bool rowOK = (hB >= 0) && (hB < HH);   // warp-uniform

    ull acc[9][2];
#pragma unroll
    for (int d = 0; d < 9; d++) { acc[d][0] = 0ull; acc[d][1] = 0ull; }

    if (rowOK) {
        const float4* pA = (const float4*)(in1 + (size_t)(b * CTOT) * CHS + h0 * WW + x0);
        const float*  base = in2 + (size_t)(b * CTOT) * CHS + hB * WW + x0;

        // Per-lane predicated window pointers; OOB lanes get stride-0 zero quad.
        const bool okL = (lane > 0), okR = (lane < 31);
        const float4* pL = okL ? (const float4*)(base - 4) : &g_zero4;
        const float4* pM = (const float4*)base;
        const float4* pR = okR ? (const float4*)(base + 4) : &g_zero4;
        const size_t sL = okL ? (size_t)CHS4 : 0;
        const size_t sR = okR ? (size_t)CHS4 : 0;

        // Distance-2 register prefetch on the three B streams (named slots).
        float4 L0 = __ldg(pL),          M0 = __ldg(pM),        R0 = __ldg(pR);
        float4 L1 = __ldg(pL + sL),     M1 = __ldg(pM + CHS4), R1 = __ldg(pR + sR);
        pL += 2 * sL;  pM += 2 * CHS4;  pR += 2 * sR;

        for (int c = 0; c < CTOT - 2; c += 2) {
            float4 L2 = __ldg(pL),      M2 = __ldg(pM),        R2 = __ldg(pR);
            float4 L3 = __ldg(pL + sL), M3 = __ldg(pM + CHS4), R3 = __ldg(pR + sR);
            float4 a0 = __ldg(pA + (size_t)c * CHS4);
            float4 a1 = __ldg(pA + (size_t)(c + 1) * CHS4);
            compute_channel(a0, L0, M0, R0, acc);
            compute_channel(a1, L1, M1, R1, acc);
            L0 = L2; M0 = M2; R0 = R2;
            L1 = L3; M1 = M3; R1 = R3;
            pL += 2 * sL;  pM += 2 * CHS4;  pR += 2 * sR;
        }
        // Tail: channels CTOT-2, CTOT-1
        {
            float4 a0 = __ldg(pA + (size_t)(CTOT - 2) * CHS4);
            float4 a1 = __ldg(pA + (size_t)(CTOT - 1) * CHS4);
            compute_channel(a0, L0, M0, R0, acc);
            compute_channel(a1, L1, M1, R1, acc);
        }
    }

    // Epilogue: out[b, warp*9+d, h0, x0..x0+3] = acc / 256  (zeros when !rowOK)
    const float inv = 1.0f / 256.0f;
#pragma unroll
    for (int d = 0; d < 9; d++) {
        const int n = warp * 9 + d;
        float* op = out + ((size_t)((b * 81 + n) * HH + h0)) * WW + x0;
        float2 u0 = upk(acc[d][0]);
        float2 u1 = upk(acc[d][1]);
        *(float4*)op = make_float4(u0.x * inv, u0.y * inv, u1.x * inv, u1.y * inv);
    }
}

extern "C" void kernel_launch(void* const* d_in, const int* in_sizes, int n_in,
                              void* d_out, int out_size)
{
    const float* in1 = (const float*)d_in[0];
    const float* in2 = (const float*)d_in[1];
    float* out = (float*)d_out;

    corr_kernel<<<BB * HH, THREADS>>>(in1, in2, out);
}